// round 17
// baseline (speedup 1.0000x reference)
#include <cuda_runtime.h>
#include <cuda_bf16.h>
#include <math.h>
#include <stdint.h>

#define BATCH 8
#define CDIM  256
#define NQD   1024
#define NKD   4096
#define SKEYS 16
#define HEADS 8
#define FFDIM 2048
#define DHD   32
#define BQTOT (BATCH*NQD)
#define CP    260   // padded smem stride (attn kernel; 16B-aligned rows)
#define HC    2048  // HEADS*CDIM
#define QB    4     // queries per attn block

typedef __nv_bfloat16 bf16;

// ---------------- scratch (device globals; no allocation allowed) ----------------
__device__ float g_keyT[BATCH*NKD*CDIM];     // key transposed (B, NK, C)
__device__ float g_qtok[BQTOT*CDIM];         // transposed query tokens (residual)
__device__ bf16  g_qin [BQTOT*CDIM];         // qtok + qpe (bf16, GEMM A)
__device__ bf16  g_m   [(size_t)BQTOT*HC];   // fused q*W2 scores operand (bf16)
__device__ int   g_sidx[BQTOT*SKEYS];        // gathered key indices (-1 = masked)
__device__ bf16  g_wkv [(size_t)BQTOT*HC];   // attn-weighted kv, flat (bf16)
__device__ float g_res1[2*BQTOT*CDIM];       // fused o-proj output (2 split-K slices)
__device__ float g_x   [BQTOT*CDIM];         // after LN1 (residual)
__device__ bf16  g_xr  [BQTOT*CDIM];         // after LN1 (bf16, GEMM A)
__device__ bf16  g_ff  [BQTOT*FFDIM];        // FFN hidden (bf16, GEMM A)
__device__ float g_y   [2*BQTOT*CDIM];       // FFN out (2 slices)
// fused / rounded weights
__device__ bf16  g_w2  [HC*CDIM];            // W2[h*256+c][e]
__device__ float g_mbias[HC];                // k_w^T q_b
__device__ bf16  g_w3  [CDIM*HC];            // W3[n][h*256+c]
__device__ float g_b3  [CDIM];               // o_b + o_w @ v_b
__device__ bf16  g_l1r [FFDIM*CDIM];
__device__ bf16  g_l2r [CDIM*FFDIM];

// ---------------- small PTX helpers ----------------
__device__ __forceinline__ uint32_t smem_u32(const void* p) {
    uint32_t a;
    asm("{ .reg .u64 t; cvta.to.shared.u64 t, %1; cvt.u32.u64 %0, t; }" : "=r"(a) : "l"(p));
    return a;
}
__device__ __forceinline__ void cp16(uint32_t s, const void* g) {
    asm volatile("cp.async.cg.shared.global [%0], [%1], 16;" :: "r"(s), "l"(g));
}
#define CP_COMMIT() asm volatile("cp.async.commit_group;" ::: "memory")
#define CP_WAIT1()  asm volatile("cp.async.wait_group 1;" ::: "memory")

#define LDSM4(R0,R1,R2,R3, ADDR) \
    asm volatile("ldmatrix.sync.aligned.m8n8.x4.shared.b16 {%0,%1,%2,%3}, [%4];" \
        : "=r"(R0), "=r"(R1), "=r"(R2), "=r"(R3) : "r"(ADDR))

__device__ __forceinline__ void mma_bf16(float* d,
                                         uint32_t a0, uint32_t a1, uint32_t a2, uint32_t a3,
                                         uint32_t b0, uint32_t b1) {
    asm volatile(
        "mma.sync.aligned.m16n8k16.row.col.f32.bf16.bf16.f32 "
        "{%0,%1,%2,%3}, {%4,%5,%6,%7}, {%8,%9}, {%0,%1,%2,%3};"
        : "+f"(d[0]), "+f"(d[1]), "+f"(d[2]), "+f"(d[3])
        : "r"(a0), "r"(a1), "r"(a2), "r"(a3), "r"(b0), "r"(b1));
}

#define PADB 72                  // bf16 elems per smem row (144B, conflict-free)
#define STAGE_H (2*128*PADB)     // narrow: bf16 elems per stage (A + B, 128+128 rows)
#define STAGE_W (384*PADB)       // wide:   bf16 elems per stage (A 128 + B 256 rows)

// ---------------- narrow bf16 GEMM: 128x128 tile, 256 thr (split-K capable) --------
template<int RELU, int OUTBF>
__global__ void __launch_bounds__(256)
k_gemm_bf(const bf16* __restrict__ A, const bf16* __restrict__ W,
          const float* __restrict__ bias, void* __restrict__ Cout,
          int N, int lda, int KS, size_t outStride) {
    extern __shared__ bf16 smh[];
    int t = threadIdx.x, lane = t & 31, wid = t >> 5;
    int wm = wid >> 1, wn = wid & 1;
    int bm = blockIdx.y * 128, bn = blockIdx.x * 128;
    int kb = blockIdx.z * KS;
    const int NC = KS >> 6;
    int qr = lane >> 2, qc = lane & 3;

    int lrowA = (lane & 7) + ((lane >> 3) & 1) * 8;
    int lsegA = (lane >> 4) * 8;
    int lrowB = ((lane >> 4) * 8) + (lane & 7);
    int lsegB = ((lane >> 3) & 1) * 8;
    uint32_t smbase = smem_u32(smh);
    uint32_t aoff = (uint32_t)(((wm*32 + lrowA)*PADB + lsegA) * 2);
    uint32_t boff = (uint32_t)((128*PADB + (wn*64 + lrowB)*PADB + lsegB) * 2);

    float acc[2][8][4];
#pragma unroll
    for (int mi = 0; mi < 2; mi++)
#pragma unroll
        for (int ni = 0; ni < 8; ni++)
#pragma unroll
            for (int j = 0; j < 4; j++) acc[mi][ni][j] = 0.f;

    {
        bf16* As = smh; bf16* Bs = smh + 128*PADB;
        for (int u = t; u < 1024; u += 256) {
            int row = u >> 3, seg = u & 7;
            cp16(smem_u32(As + row*PADB + seg*8), A + (size_t)(bm + row)*lda + kb + seg*8);
            cp16(smem_u32(Bs + row*PADB + seg*8), W + (size_t)(bn + row)*lda + kb + seg*8);
        }
    }
    CP_COMMIT();

    for (int c = 0; c < NC; c++) {
        __syncthreads();
        if (c + 1 < NC) {
            bf16* As = smh + ((c+1)&1)*STAGE_H;
            bf16* Bs = As + 128*PADB;
            int k0 = kb + (c+1)*64;
            for (int u = t; u < 1024; u += 256) {
                int row = u >> 3, seg = u & 7;
                cp16(smem_u32(As + row*PADB + seg*8), A + (size_t)(bm + row)*lda + k0 + seg*8);
                cp16(smem_u32(Bs + row*PADB + seg*8), W + (size_t)(bn + row)*lda + k0 + seg*8);
            }
        }
        CP_COMMIT();
        CP_WAIT1();
        __syncthreads();

        uint32_t sb = smbase + ((c & 1) ? (uint32_t)(STAGE_H*2) : 0u);
        uint32_t aB = sb + aoff, bB = sb + boff;
#pragma unroll
        for (int kk = 0; kk < 4; kk++) {
            uint32_t a0[4], a1[4], bf[8][2];
            LDSM4(a0[0], a0[1], a0[2], a0[3], aB + kk*32);
            LDSM4(a1[0], a1[1], a1[2], a1[3], aB + 16*PADB*2 + kk*32);
#pragma unroll
            for (int j = 0; j < 4; j++)
                LDSM4(bf[2*j][0], bf[2*j][1], bf[2*j+1][0], bf[2*j+1][1],
                      bB + j*16*PADB*2 + kk*32);
#pragma unroll
            for (int ni = 0; ni < 8; ni++) {
                mma_bf16(acc[0][ni], a0[0], a0[1], a0[2], a0[3], bf[ni][0], bf[ni][1]);
                mma_bf16(acc[1][ni], a1[0], a1[1], a1[2], a1[3], bf[ni][0], bf[ni][1]);
            }
        }
    }

    bool addb = (blockIdx.z == 0);
#pragma unroll
    for (int mi = 0; mi < 2; mi++) {
        int r0 = bm + wm*32 + mi*16 + qr;
#pragma unroll
        for (int ni = 0; ni < 8; ni++) {
            int cn = bn + wn*64 + ni*8 + qc*2;
            float b0 = addb ? bias[cn] : 0.f, b1 = addb ? bias[cn+1] : 0.f;
            float v0 = acc[mi][ni][0] + b0, v1 = acc[mi][ni][1] + b1;
            float v2 = acc[mi][ni][2] + b0, v3 = acc[mi][ni][3] + b1;
            if (RELU) { v0=fmaxf(v0,0.f); v1=fmaxf(v1,0.f); v2=fmaxf(v2,0.f); v3=fmaxf(v3,0.f); }
            if (OUTBF) {
                bf16* C = (bf16*)Cout;
                *(__nv_bfloat162*)&C[(size_t)r0*N + cn]     = __floats2bfloat162_rn(v0, v1);
                *(__nv_bfloat162*)&C[(size_t)(r0+8)*N + cn] = __floats2bfloat162_rn(v2, v3);
            } else {
                float* C = (float*)Cout + (size_t)blockIdx.z * outStride;
                *(float2*)&C[(size_t)r0*N + cn]     = make_float2(v0, v1);
                *(float2*)&C[(size_t)(r0+8)*N + cn] = make_float2(v2, v3);
            }
        }
    }
}

// ---------------- wide bf16 GEMM: 128x256 tile, 512 thr (no split-K) ---------------
template<int RELU, int OUTBF>
__global__ void __launch_bounds__(512)
k_gemm_w(const bf16* __restrict__ A, const bf16* __restrict__ W,
         const float* __restrict__ bias, void* __restrict__ Cout,
         int N, int lda, int K) {
    extern __shared__ bf16 smh[];
    int t = threadIdx.x, lane = t & 31, wid = t >> 5;   // 16 warps
    int wm = wid >> 2, wn = wid & 3;          // 4x4 warp grid, warp tile 32x64
    int bm = blockIdx.y * 128, bn = blockIdx.x * 256;
    const int NC = K >> 6;
    int qr = lane >> 2, qc = lane & 3;

    int lrowA = (lane & 7) + ((lane >> 3) & 1) * 8;
    int lsegA = (lane >> 4) * 8;
    int lrowB = ((lane >> 4) * 8) + (lane & 7);
    int lsegB = ((lane >> 3) & 1) * 8;
    uint32_t smbase = smem_u32(smh);
    uint32_t aoff = (uint32_t)(((wm*32 + lrowA)*PADB + lsegA) * 2);
    uint32_t boff = (uint32_t)((128*PADB + (wn*64 + lrowB)*PADB + lsegB) * 2);

    float acc[2][8][4];
#pragma unroll
    for (int mi = 0; mi < 2; mi++)
#pragma unroll
        for (int ni = 0; ni < 8; ni++)
#pragma unroll
            for (int j = 0; j < 4; j++) acc[mi][ni][j] = 0.f;

    {
        bf16* As = smh; bf16* Bs = smh + 128*PADB;
#pragma unroll
        for (int u = t; u < 1024; u += 512) {
            int row = u >> 3, seg = u & 7;
            cp16(smem_u32(As + row*PADB + seg*8), A + (size_t)(bm + row)*lda + seg*8);
        }
#pragma unroll
        for (int u = t; u < 2048; u += 512) {
            int row = u >> 3, seg = u & 7;
            cp16(smem_u32(Bs + row*PADB + seg*8), W + (size_t)(bn + row)*lda + seg*8);
        }
    }
    CP_COMMIT();

    for (int c = 0; c < NC; c++) {
        __syncthreads();
        if (c + 1 < NC) {
            bf16* As = smh + ((c+1)&1)*STAGE_W;
            bf16* Bs = As + 128*PADB;
            int k0 = (c+1)*64;
#pragma unroll
            for (int u = t; u < 1024; u += 512) {
                int row = u >> 3, seg = u & 7;
                cp16(smem_u32(As + row*PADB + seg*8), A + (size_t)(bm + row)*lda + k0 + seg*8);
            }
#pragma unroll
            for (int u = t; u < 2048; u += 512) {
                int row = u >> 3, seg = u & 7;
                cp16(smem_u32(Bs + row*PADB + seg*8), W + (size_t)(bn + row)*lda + k0 + seg*8);
            }
        }
        CP_COMMIT();
        CP_WAIT1();
        __syncthreads();

        uint32_t sb = smbase + ((c & 1) ? (uint32_t)(STAGE_W*2) : 0u);
        uint32_t aB = sb + aoff, bB = sb + boff;
#pragma unroll
        for (int kk = 0; kk < 4; kk++) {
            uint32_t a0[4], a1[4], bf[8][2];
            LDSM4(a0[0], a0[1], a0[2], a0[3], aB + kk*32);
            LDSM4(a1[0], a1[1], a1[2], a1[3], aB + 16*PADB*2 + kk*32);
#pragma unroll
            for (int j = 0; j < 4; j++)
                LDSM4(bf[2*j][0], bf[2*j][1], bf[2*j+1][0], bf[2*j+1][1],
                      bB + j*16*PADB*2 + kk*32);
#pragma unroll
            for (int ni = 0; ni < 8; ni++) {
                mma_bf16(acc[0][ni], a0[0], a0[1], a0[2], a0[3], bf[ni][0], bf[ni][1]);
                mma_bf16(acc[1][ni], a1[0], a1[1], a1[2], a1[3], bf[ni][0], bf[ni][1]);
            }
        }
    }

#pragma unroll
    for (int mi = 0; mi < 2; mi++) {
        int r0 = bm + wm*32 + mi*16 + qr;
#pragma unroll
        for (int ni = 0; ni < 8; ni++) {
            int cn = bn + wn*64 + ni*8 + qc*2;
            float b0 = bias[cn], b1 = bias[cn+1];
            float v0 = acc[mi][ni][0] + b0, v1 = acc[mi][ni][1] + b1;
            float v2 = acc[mi][ni][2] + b0, v3 = acc[mi][ni][3] + b1;
            if (RELU) { v0=fmaxf(v0,0.f); v1=fmaxf(v1,0.f); v2=fmaxf(v2,0.f); v3=fmaxf(v3,0.f); }
            if (OUTBF) {
                bf16* C = (bf16*)Cout;
                *(__nv_bfloat162*)&C[(size_t)r0*N + cn]     = __floats2bfloat162_rn(v0, v1);
                *(__nv_bfloat162*)&C[(size_t)(r0+8)*N + cn] = __floats2bfloat162_rn(v2, v3);
            } else {
                float* C = (float*)Cout;
                *(float2*)&C[(size_t)r0*N + cn]     = make_float2(v0, v1);
                *(float2*)&C[(size_t)(r0+8)*N + cn] = make_float2(v2, v3);
            }
        }
    }
}

// ---------------- elementwise f32 -> bf16 (vectorized x4) ----------------
__global__ void k_round(const float* __restrict__ in, bf16* __restrict__ out, int n4) {
    int i = blockIdx.x * 256 + threadIdx.x;
    if (i < n4) {
        float4 v = ((const float4*)in)[i];
        __nv_bfloat162 lo = __floats2bfloat162_rn(v.x, v.y);
        __nv_bfloat162 hi = __floats2bfloat162_rn(v.z, v.w);
        uint2 u; u.x = *(uint32_t*)&lo; u.y = *(uint32_t*)&hi;
        ((uint2*)out)[i] = u;
    }
}

// ---------------- W2 prep: W2[h*256+c][e] = sum_d q_w[hd,e]*k_w[hd,c]; mbias = k_w^T q_b
__global__ void __launch_bounds__(256)
k_prep_w2(const float* __restrict__ qw, const float* __restrict__ kw,
          const float* __restrict__ qb) {
    __shared__ float kc[32][33];
    __shared__ float qbs[32];
    int h = blockIdx.x >> 3, c0 = (blockIdx.x & 7) * 32;
    int t = threadIdx.x;
    for (int u = t; u < 1024; u += 256) {
        int d = u >> 5, cl = u & 31;
        kc[d][cl] = kw[(size_t)(h*32 + d)*CDIM + c0 + cl];
    }
    if (t < 32) qbs[t] = qb[h*32 + t];
    __syncthreads();
    float qe[32];
#pragma unroll
    for (int d = 0; d < 32; d++) qe[d] = qw[(size_t)(h*32 + d)*CDIM + t];
    for (int cl = 0; cl < 32; cl++) {
        float s = 0.f;
#pragma unroll
        for (int d = 0; d < 32; d++) s += qe[d]*kc[d][cl];
        g_w2[(size_t)(h*256 + c0 + cl)*CDIM + t] = __float2bfloat16_rn(s);
    }
    if (t < 32) {
        float s = 0.f;
#pragma unroll
        for (int d = 0; d < 32; d++) s += kc[d][t]*qbs[d];
        g_mbias[h*256 + c0 + t] = s;
    }
}

// ---------------- W3 prep: W3[n][h*256+c] = sum_d o_w[n,hd]*v_w[hd,c] ----------------
__global__ void __launch_bounds__(256)
k_prep_w3(const float* __restrict__ ow, const float* __restrict__ vw) {
    __shared__ float os[64][33];
    int h = blockIdx.x >> 2, n0 = (blockIdx.x & 3) * 64;
    int t = threadIdx.x;
    for (int u = t; u < 2048; u += 256) {
        int nl = u >> 5, d = u & 31;
        os[nl][d] = ow[(size_t)(n0 + nl)*CDIM + h*32 + d];
    }
    float vd[32];
#pragma unroll
    for (int d = 0; d < 32; d++) vd[d] = vw[(size_t)(h*32 + d)*CDIM + t];
    __syncthreads();
    for (int nl = 0; nl < 64; nl++) {
        float s = 0.f;
#pragma unroll
        for (int d = 0; d < 32; d++) s += os[nl][d]*vd[d];
        g_w3[(size_t)(n0 + nl)*HC + h*256 + t] = __float2bfloat16_rn(s);
    }
}

// ---------------- b3 prep: b3[n] = o_b[n] + o_w[n,:] @ v_b ----------------
__global__ void __launch_bounds__(256)
k_prep_b3(const float* __restrict__ ow, const float* __restrict__ ob,
          const float* __restrict__ vb) {
    __shared__ float vbs[256];
    int t = threadIdx.x;
    vbs[t] = vb[t];
    __syncthreads();
    float s = ob[t];
    for (int k = 0; k < 256; k++) s += ow[(size_t)t*CDIM + k]*vbs[k];
    g_b3[t] = s;
}

// ---------------- transpose key (B,C,NK) -> (B,NK,C) ----------------
__global__ void k_transpose_key(const float* __restrict__ key) {
    __shared__ float tile[32][33];
    int b = blockIdx.z;
    int c0 = blockIdx.y * 32, n0 = blockIdx.x * 32;
    int tx = threadIdx.x, ty = threadIdx.y;
#pragma unroll
    for (int j = 0; j < 4; j++)
        tile[ty + 8*j][tx] = key[(b*CDIM + c0 + ty + 8*j)*NKD + n0 + tx];
    __syncthreads();
#pragma unroll
    for (int j = 0; j < 4; j++)
        g_keyT[(b*NKD + n0 + ty + 8*j)*CDIM + c0 + tx] = tile[tx][ty + 8*j];
}

// ---------------- build qtok + qin (query transpose + qpe) ----------------
__global__ void k_build_q(const float* __restrict__ query,
                          const float* __restrict__ query_pos,
                          const float* __restrict__ qpe_w,
                          const float* __restrict__ qpe_b) {
    __shared__ float tile[32][33];
    int b = blockIdx.z;
    int c0 = blockIdx.y * 32, n0 = blockIdx.x * 32;
    int tx = threadIdx.x, ty = threadIdx.y;
#pragma unroll
    for (int j = 0; j < 4; j++)
        tile[ty + 8*j][tx] = query[(b*CDIM + c0 + ty + 8*j)*NQD + n0 + tx];
    __syncthreads();
#pragma unroll
    for (int j = 0; j < 4; j++) {
        int nq = n0 + ty + 8*j, c = c0 + tx;
        int bq = b*NQD + nq;
        float qt = tile[tx][ty + 8*j];
        const float* qp = query_pos + (size_t)bq*6;
        float pe = qpe_b[c];
#pragma unroll
        for (int jj = 0; jj < 6; jj++) pe += qp[jj] * qpe_w[c*6 + jj];
        g_qtok[bq*CDIM + c] = qt;
        g_qin [bq*CDIM + c] = __float2bfloat16_rn(qt + pe);
    }
}

// ---------------- box query: 32 queries/block, first 16 inside keys ---------------
__global__ void __launch_bounds__(1024)
k_boxquery(const float* __restrict__ key_pos,
           const float* __restrict__ query_pos) {
    __shared__ float kp[NKD*3];   // exactly 48KB
    int b = blockIdx.y;
    int t = threadIdx.x;
#pragma unroll
    for (int i = 0; i < 12; i++)
        kp[t + 1024*i] = key_pos[(size_t)b*NKD*3 + t + 1024*i];
    __syncthreads();

    int w = t >> 5, lane = t & 31;
    int q = blockIdx.x * 32 + w;
    int bq = b*NQD + q;
    const float* qp = query_pos + (size_t)bq*6;
    float cx = qp[0], cy = qp[1], cz = qp[2];
    float hx = 0.5f*qp[3], hy = 0.5f*qp[4], hz = 0.5f*qp[5];

    int count = 0;
    for (int base = 0; base < NKD && count < SKEYS; base += 32) {
        int k = base + lane;
        float dx = fabsf(kp[k*3+0]-cx);
        float dy = fabsf(kp[k*3+1]-cy);
        float dz = fabsf(kp[k*3+2]-cz);
        bool inside = (dx <= hx) && (dy <= hy) && (dz <= hz);
        unsigned bal = __ballot_sync(0xffffffffu, inside);
        int nb = __popc(bal);
        if (inside) {
            int rank = __popc(bal & ((1u << lane) - 1u));
            if (count + rank < SKEYS) g_sidx[bq*SKEYS + count + rank] = k;
        }
        count += nb;
        if (count > SKEYS) count = SKEYS;
    }
    if (lane < SKEYS && lane >= count)
        g_sidx[bq*SKEYS + lane] = (lane == 0) ? 0 : -1;
}

// ---------------- fused gather + attention core (4 queries, 256 threads) ------------
__global__ void __launch_bounds__(256)
k_attn(const float* __restrict__ key_pos,
       const float* __restrict__ query_pos,
       const float* __restrict__ kpe_w,
       const float* __restrict__ kpe_b) {
    extern __shared__ float sm[];
    float* kv = sm;                     // [QB][16][CP]
    float* mb = kv + QB*16*CP;          // [QB][8][CP]   (m rows from g_m)
    float* at = mb + QB*8*CP;           // [QB][8][16]   (scores, then attn)
    float* pes = at + QB*128;           // [4][256]  kpe SoA: w0,w1,w2,b
    float* qc = pes + 4*256;            // [QB][4]
    int*  sid = (int*)(qc + 4*QB);      // [QB][16]

    int t = threadIdx.x, lane = t & 31, w = t >> 5;   // 8 warps
    int bq0 = blockIdx.x * QB;
    int b = bq0 >> 10;   // NQ=1024

    if (t < QB*SKEYS) sid[t] = g_sidx[bq0*SKEYS + t];
    if (t < QB*3) { int g = t/3, j = t%3; qc[g*4 + j] = query_pos[(size_t)(bq0+g)*6 + j]; }
    {   // kpe SoA staging
        pes[0*256 + t] = kpe_w[t*3 + 0];
        pes[1*256 + t] = kpe_w[t*3 + 1];
        pes[2*256 + t] = kpe_w[t*3 + 2];
        pes[3*256 + t] = kpe_b[t];
    }
    // load m rows (bf16 x8): QB*8*32 = 1024 uint4 loads
#pragma unroll
    for (int i = 0; i < 4; i++) {
        int v = t + 256*i;
        int g = v >> 8, rem = v & 255;       // rem = h*32 + c8
        int h = rem >> 5, c8 = rem & 31;
        uint4 u = *(const uint4*)&g_m[(size_t)(bq0 + g)*HC + h*256 + c8*8];
        float* dst = mb + (g*8 + h)*CP + c8*8;
        float2 f0 = __bfloat1622float2(*(__nv_bfloat162*)&u.x);
        float2 f1 = __bfloat1622float2(*(__nv_bfloat162*)&u.y);
        float2 f2 = __bfloat1622float2(*(__nv_bfloat162*)&u.z);
        float2 f3 = __bfloat1622float2(*(__nv_bfloat162*)&u.w);
        dst[0] = f0.x; dst[1] = f0.y; dst[2] = f1.x; dst[3] = f1.y;
        dst[4] = f2.x; dst[5] = f2.y; dst[6] = f3.x; dst[7] = f3.y;
    }
    __syncthreads();

    // phase 1: gather kv = keyT[idx] + kpe(gxyz)   (warp = (g, s-half))
    {
        int g = w >> 1, sh = w & 1;
        float qcx = qc[g*4+0], qcy = qc[g*4+1], qcz = qc[g*4+2];
        for (int si = 0; si < 8; si++) {
            int s = sh*8 + si;
            int v = sid[g*16 + s];
            int kidx = v < 0 ? 0 : v;
            int base = b*NKD + kidx;
            float gx = key_pos[base*3+0] - qcx;
            float gy = key_pos[base*3+1] - qcy;
            float gz = key_pos[base*3+2] - qcz;
            const float4* krow4 = (const float4*)(g_keyT + (size_t)base*CDIM);
            float* kvrow = kv + (g*16 + s)*CP;
#pragma unroll
            for (int i = 0; i < 2; i++) {
                int c4 = lane + 32*i;
                float4 kr = krow4[c4];
                float4 w0 = *(const float4*)&pes[0*256 + 4*c4];
                float4 w1 = *(const float4*)&pes[1*256 + 4*c4];
                float4 w2 = *(const float4*)&pes[2*256 + 4*c4];
                float4 bb = *(const float4*)&pes[3*256 + 4*c4];
                float4 r;
                r.x = kr.x + bb.x + gx*w0.x + gy*w1.x + gz*w2.x;
                r.y = kr.y + bb.y + gx*w0.y + gy*w1.y + gz*w2.y;
                r.z = kr.z + bb.z + gx*w0.z + gy*w1.z + gz*w2.z;
                r.w = kr.w + bb.w + gx*w0.w + gy*w1.w + gz*w2.w;
                *(float4*)&kvrow[4*c4] = r;
            }
        }
    }
    __syncthreads();

    // phase 3: scores[g][h][s] = m[g][h] . kv[g][s]
    {
        int g = w >> 1, hh = w & 1;
        int h = hh*4 + (lane >> 3), s0 = lane & 7;
        float sc[2] = {0.f, 0.f};
        const float4* m4 = (const float4*)(mb + (g*8 + h)*CP);
        const float4* kv0 = (const float4*)(kv + (g*16 + s0)*CP);
        const float4* kv1 = (const float4*)(kv + (g*16 + s0 + 8)*CP);
        for (int c4 = 0; c4 < 64; c4++) {
            float4 mv = m4[c4];
            float4 k0 = kv0[c4], k1 = kv1[c4];
            sc[0] += mv.x*k0.x + mv.y*k0.y + mv.z*k0.z + mv.w*k0.w;
            sc[1] += mv.x*k1.x + mv.y*k1.y + mv.z*k1.z + mv.w*k1.w;
        }
        at[(g*8 + h)*16 + s0]     = sc[0];
        at[(g*8 + h)*16 + s0 + 8] = sc[1];
    }
    __syncthreads();

    // phase 4: masked softmax (one thread per (g,h))
    if (t < QB*8) {
        int g = t >> 3, h = t & 7;
        float* row = at + (g*8 + h)*16;
        const int* sg = sid + g*16;
        const float scl = 0.17677669529663687f;   // 1/sqrt(32)
        float sv[16];
        float mx = -3.0e38f;
#pragma unroll
        for (int s = 0; s < 16; s++) {
            sv[s] = (sg[s] < 0) ? -3.0e38f : row[s]*scl;
            mx = fmaxf(mx, sv[s]);
        }
        float sum = 0.f;
#pragma unroll
        for (int s = 0; s < 16; s++) {
            float e = (sg[s] < 0) ? 0.f : __expf(sv[s] - mx);
            sv[s] = e; sum += e;
        }
        float inv = 1.f/sum;
#pragma unroll
        for (int s = 0; s < 16; s++) row[s] = sv[s]*inv;
    }
    __syncthreads();

    // phase 5: wkv -> g_wkv (bf16)
    {
        int g = w >> 1, ch = w & 1;
        int cb = ch*128 + lane*4;
        float acc[8][4];
#pragma unroll
        for (int i = 0; i < 8; i++)
#pragma unroll
            for (int j = 0; j < 4; j++) acc[i][j] = 0.f;
        for (int s = 0; s < 16; s++) {
            float av[8];
#pragma unroll
            for (int h = 0; h < 8; h++) av[h] = at[(g*8 + h)*16 + s];
            float4 kk = *(const float4*)(kv + (g*16 + s)*CP + cb);
#pragma unroll
            for (int h = 0; h < 8; h++) {
                acc[h][0] += av[h]*kk.x; acc[h][1] += av[h]*kk.y;
                acc[h][2] += av[h]*kk.z; acc[h][3] += av[h]*kk.w;
            }
        }
        bf16* dst = g_wkv + (size_t)(bq0 + g)*HC + cb;
#pragma unroll
        for (int h = 0; h < 8; h++) {
            __nv_bfloat162 lo = __floats2bfloat162_rn(acc[h][0], acc[h][1]);
            __nv_bfloat162 hi = __floats2bfloat162_rn(acc[h][2], acc[h][3]);
            uint2 u;
            u.x = *(uint32_t*)&lo; u.y = *(uint32_t*)&hi;
            *(uint2*)(dst + h*256) = u;
        }
    }
}

// ---------------- layernorm of (ra + rb + rc), writes full f32 + bf16 ----------
__global__ void k_ln(const float* __restrict__ ra, const float* __restrict__ rb,
                     const float* __restrict__ rc,
                     const float* __restrict__ gamma, const float* __restrict__ beta,
                     float* __restrict__ out, bf16* __restrict__ outr) {
    int bq = blockIdx.x * 8 + (threadIdx.x >> 5);
    int lane = threadIdx.x & 31;
    float v[8];
    float s = 0.f;
#pragma unroll
    for (int i = 0; i < 8; i++) {
        int c = lane + 32*i;
        v[i] = ra[(size_t)bq*CDIM + c] + rb[(size_t)bq*CDIM + c] + rc[(size_t)bq*CDIM + c];
        s += v[i];
    }
#pragma unroll
    for (int o = 16; o; o >>= 1) s += __shfl_xor_sync(0xffffffffu, s, o);
    float mean = s * (1.f/256.f);
    float vs = 0.f;
#pragma unroll
    for (int i = 0; i < 8; i++) { float d = v[i]-mean; vs += d*d; }
#pragma unroll
    for (int o = 16; o; o >>= 1) vs += __shfl_xor_sync(0xffffffffu, vs, o);
    float rstd = rsqrtf(vs*(1.f/256.f) + 1e-5f);
#pragma unroll
    for (int i = 0; i < 8; i++) {
        int c = lane + 32*i;
        float r = (v[i]-mean)*rstd*gamma[c] + beta[c];
        out [(size_t)bq*CDIM + c] = r;
        outr[(size_t)bq*CDIM + c] = __float2bfloat16_rn(r);
    }
}

// ---------------- final LN2 + coalesced transpose to (B, C, NQ): 32 bq/block ------
__global__ void __launch_bounds__(256)
k_ln_out(const float* __restrict__ ra, const float* __restrict__ rb,
         const float* __restrict__ rc,
         const float* __restrict__ gamma, const float* __restrict__ beta,
         float* __restrict__ out) {
    __shared__ float tile[256][33];
    int t = threadIdx.x, lane = t & 31, w = t >> 5;
    int bq0 = blockIdx.x * 32;
    int b = bq0 >> 10, nq0 = bq0 & 1023;

    for (int rep = 0; rep < 4; rep++) {
        int bqL = w*4 + rep;
        size_t base = (size_t)(bq0 + bqL)*CDIM;
        float v[8];
        float s = 0.f;
#pragma unroll
        for (int i = 0; i < 8; i++) {
            int c = lane + 32*i;
            v[i] = ra[base + c] + rb[base + c] + rc[base + c];
            s += v[i];
        }
#pragma unroll
        for (int o = 16; o; o >>= 1) s += __shfl_xor_sync(0xffffffffu, s, o);
        float mean = s * (1.f/256.f);
        float vs = 0.f;
#pragma unroll
        for (int i = 0; i < 8; i++) { float d = v[i]-mean; vs += d*d; }
#pragma unroll
        for (int o = 16; o; o >>= 1) vs += __shfl_xor_sync(0xffffffffu, vs, o);
        float rstd = rsqrtf(vs*(1.f/256.f) + 1e-5f);
#pragma unroll
        for (int i = 0; i < 8; i++) {
            int c = lane + 32*i;
            tile[c][bqL] = (v[i]-mean)*rstd*gamma[c] + beta[c];
        }
    }
    __syncthreads();

#pragma unroll
    for (int i = 0; i < 32; i++) {
        int c = w*32 + i;
        out[((size_t)b*CDIM + c)*NQD + nq0 + lane] = tile[c][lane];
    }
}

// ---------------- launch ----------------
extern "C" void kernel_launch(void* const* d_in, const int* in_sizes, int n_in,
                              void* d_out, int out_size) {
    const float* query     = (const float*)d_in[0];
    const float* key       = (const float*)d_in[1];
    const float* query_pos = (const float*)d_in[2];
    const float* key_pos   = (const float*)d_in[3];
    const float* q_w   = (const float*)d_in[4];
    const float* q_b   = (const float*)d_in[5];
    const float* k_w   = (const float*)d_in[6];
    // d_in[7] = k_b: cancels in softmax (uniform shift per (bq,h))
    const float* v_w   = (const float*)d_in[8];
    const float* v_b   = (const float*)d_in[9];
    const float* o_w   = (const float*)d_in[10];
    const float* o_b   = (const float*)d_in[11];
    const float* lin1_w = (const float*)d_in[12];
    const float* lin1_b = (const float*)d_in[13];
    const float* lin2_w = (const float*)d_in[14];
    const float* lin2_b = (const float*)d_in[15];
    const float* n1_g = (const float*)d_in[16];
    const float* n1_b = (const float*)d_in[17];
    const float* n2_g = (const float*)d_in[18];
    const float* n2_b = (const float*)d_in[19];
    const float* qpe_w = (const float*)d_in[20];
    const float* qpe_b = (const float*)d_in[21];
    const float* kpe_w = (const float*)d_in[22];
    const float* kpe_b = (const float*)d_in[23];

    void *p_qin, *p_m, *p_wkv, *p_res1, *p_qtok, *p_x, *p_xr, *p_ff, *p_y;
    void *p_w2, *p_w3, *p_mbias, *p_b3, *p_l1r, *p_l2r;
    cudaGetSymbolAddress(&p_qin,  g_qin);
    cudaGetSymbolAddress(&p_m,    g_m);
    cudaGetSymbolAddress(&p_wkv,  g_wkv);
    cudaGetSymbolAddress(&p_res1, g_res1);
    cudaGetSymbolAddress(&p_qtok, g_qtok);
    cudaGetSymbolAddress(&p_x,    g_x);
    cudaGetSymbolAddress(&p_xr,   g_xr);
    cudaGetSymbolAddress(&p_ff,   g_ff);
    cudaGetSymbolAddress(&p_y,    g_y);
    cudaGetSymbolAddress(&p_w2,   g_w2);
    cudaGetSymbolAddress(&p_w3,   g_w3);
    cudaGetSymbolAddress(&p_mbias, g_mbias);
    cudaGetSymbolAddress(&p_b3,   g_b3);
    cudaGetSymbolAddress(&p_l1r,  g_l1r);
    cudaGetSymbolAddress(&p_l2r,  g_l2r);

    const size_t SLICE = (size_t)BQTOT * CDIM;

    const int attn_smem = (QB*16*CP + QB*8*CP + QB*128 + 4*256 + 4*QB)*4 + QB*16*4;
    cudaFuncSetAttribute(k_attn, cudaFuncAttributeMaxDynamicSharedMemorySize, attn_smem);

    const int gemm_smem = 2 * STAGE_H * 2;    // 73,728 bytes (narrow)
    cudaFuncSetAttribute(k_gemm_bf<0,0>, cudaFuncAttributeMaxDynamicSharedMemorySize, gemm_smem);
    const int gemw_smem = 2 * STAGE_W * 2;    // 110,592 bytes (wide)
    cudaFuncSetAttribute(k_gemm_w<0,1>, cudaFuncAttributeMaxDynamicSharedMemorySize, gemw_smem);
    cudaFuncSetAttribute(k_gemm_w<1,1>, cudaFuncAttributeMaxDynamicSharedMemorySize, gemw_smem);

    // streams/events: 3 side streams (R10/R13 passing topology)
    static cudaStream_t s1 = nullptr, s2 = nullptr, s3 = nullptr;
    static cudaEvent_t  evR = nullptr, e1 = nullptr, e2 = nullptr, e3 = nullptr;
    if (!s1) {
        cudaStreamCreateWithFlags(&s1, cudaStreamNonBlocking);
        cudaStreamCreateWithFlags(&s2, cudaStreamNonBlocking);
        cudaStreamCreateWithFlags(&s3, cudaStreamNonBlocking);
        cudaEventCreateWithFlags(&evR, cudaEventDisableTiming);
        cudaEventCreateWithFlags(&e1,  cudaEventDisableTiming);
        cudaEventCreateWithFlags(&e2,  cudaEventDisableTiming);
        cudaEventCreateWithFlags(&e3,  cudaEventDisableTiming);
    }

    // ---- fork ----
    cudaEventRecord(evR, 0);
    cudaStreamWaitEvent(s1, evR, 0);
    cudaStreamWaitEvent(s2, evR, 0);
    cudaStreamWaitEvent(s3, evR, 0);

    // s1: key transpose
    k_transpose_key<<<dim3(NKD/32, CDIM/32, BATCH), dim3(32,8), 0, s1>>>(key);
    // s3: box query
    k_boxquery<<<dim3(NQD/32, BATCH), 1024, 0, s3>>>(key_pos, query_pos);
    // s2: FFN weight rounds + fused W3/b3 prep
    k_round<<<FFDIM*CDIM/1024, 256, 0, s2>>>(lin1_w, (bf16*)p_l1r, FFDIM*CDIM/4);
    k_round<<<CDIM*FFDIM/1024, 256, 0, s2>>>(lin2_w, (bf16*)p_l2r, CDIM*FFDIM/4);
    k_prep_w3<<<32, 256, 0, s2>>>(o_w, v_w);
    k_prep_b3<<<1, 256, 0, s2>>>(o_w, o_b, v_b);
    // default: build_q -> W2 prep -> m-GEMM (wide, bf16 out)
    k_build_q<<<dim3(NQD/32, CDIM/32, BATCH), dim3(32,8)>>>(query, query_pos, qpe_w, qpe_b);
    k_prep_w2<<<64, 256>>>(q_w, k_w, q_b);
    k_gemm_w<0,1><<<dim3(HC/256, BQTOT/128), 512, gemw_smem>>>(
        (const bf16*)p_qin, (const bf16*)p_w2, (const float*)p_mbias, p_m,
        HC, CDIM, 256);

    // ---- join s1, s3 -> attn ----
    cudaEventRecord(e1, s1);
    cudaEventRecord(e3, s3);
    cudaStreamWaitEvent(0, e1, 0);
    cudaStreamWaitEvent(0, e3, 0);
    k_attn<<<BQTOT/QB, 256, attn_smem>>>(key_pos, query_pos, kpe_w, kpe_b);

    // ---- join s2 -> fused o-projection: res1 = wkv @ W3^T + b3 (split-K x2) ----
    cudaEventRecord(e2, s2);
    cudaStreamWaitEvent(0, e2, 0);
    k_gemm_bf<0,0><<<dim3(CDIM/128, BQTOT/128, 2), 256, gemm_smem>>>(
        (const bf16*)p_wkv, (const bf16*)p_w3, (const float*)p_b3, p_res1,
        CDIM, HC, 1024, SLICE);

    // LN1(qtok + res1a + res1b) -> x (f32) + xr (bf16)
    k_ln<<<BQTOT/8, 256>>>((const float*)p_qtok, (const float*)p_res1,
                           (const float*)p_res1 + SLICE, n1_g, n1_b,
                           (float*)p_x, (bf16*)p_xr);

    // FFN: lin1 wide (relu, bf16 out), lin2 narrow split-K
    k_gemm_w<1,1><<<dim3(FFDIM/256, BQTOT/128), 512, gemw_smem>>>(
        (const bf16*)p_xr, (const bf16*)p_l1r, lin1_b, p_ff,
        FFDIM, CDIM, 256);
    k_gemm_bf<0,0><<<dim3(CDIM/128, BQTOT/128, 2), 256, gemm_smem>>>(
        (const bf16*)p_ff, (const bf16*)p_l2r, lin2_b, p_y,
        CDIM, FFDIM, 1024, SLICE);

    // LN2(x + y0 + y1) + coalesced transpose out
    k_ln_out<<<BQTOT/32, 256>>>((const float*)p_x, (const float*)p_y,
                                (const float*)p_y + SLICE, n2_g, n2_b, (float*)d_out);
}